// round 5
// baseline (speedup 1.0000x reference)
#include <cuda_runtime.h>
#include <math.h>

#define PI_F 3.14159265358979323846f

// One block per batch image (128 blocks x 512 threads).
// 2 threads per patch: thread parity e holds the 8 amplitudes with amp-index
// bit0 == e (qubit 3 split). Gates on q0..q2 + 2 ring CNOTs are thread-local;
// q3 gate and CNOT(q2->q3) exchange via shfl.bfly(1); CNOT(q3->q0) is a
// predicated local swap on e==1. Doubles circuit-phase occupancy vs 1 thr/patch.
__global__ __launch_bounds__(512, 1) void qnet_kernel(
    const float* __restrict__ x,      // [128,1,28,28]
    const float* __restrict__ weight, // [60]
    const float* __restrict__ fc1_w,  // [64,784]
    const float* __restrict__ fc1_b,  // [64]
    const float* __restrict__ fc2_w,  // [10,64]
    const float* __restrict__ fc2_b,  // [10]
    float* __restrict__ out)          // [128,10]
{
    __shared__ float4 ssu2[20];       // (x=ar, y=ai, z=br, w=bi) per (layer*4 + qubit)
    __shared__ float sfeat[784];
    __shared__ float sh[64];

    const int t = threadIdx.x;
    const int b = blockIdx.x;

    // U = Ry(c)*Rz(bb)*Ry(a) = [[alpha, -conj(beta)],[beta, conj(alpha)]]
    if (t < 20) {
        const int layer = t >> 2, q = t & 3;
        const int base = layer * 12;
        float sa, ca, sb, cb, sc, cc;
        sincosf(0.5f * weight[base + q],     &sa, &ca);
        sincosf(0.5f * weight[base + 4 + q], &sb, &cb);
        sincosf(0.5f * weight[base + 8 + q], &sc, &cc);
        ssu2[t] = make_float4( cb * (cc * ca - sc * sa),
                              -sb * (cc * ca + sc * sa),
                               cb * (sc * ca + cc * sa),
                               sb * (cc * sa - sc * ca));
    }
    __syncthreads();

    if (t < 392) {
        const int patch = t >> 1;
        const int e = t & 1;                      // which half of the state
        const float s = e ? 1.f : -1.f;           // sign for q3-gate formulas
        // shfl mask: warps 0..11 full, warp 12 has lanes 0..7 active (392=12*32+8)
        const unsigned wmask = ((t >> 5) < 12) ? 0xffffffffu : 0x000000ffu;

        const int pi_ = patch / 14, pj = patch % 14;
        const float* xb = x + b * 784 + (2 * pi_) * 28 + 2 * pj;
        const float px0 = xb[0], px1 = xb[1], px2 = xb[28], px3 = xb[29];

        // Rx(2*pi*x)|0> = (cos(pi x), -i sin(pi x)); apply layer-0 U_q directly.
        float cx[4], sx[4];
        sincosf(PI_F * px0, &sx[0], &cx[0]);
        sincosf(PI_F * px1, &sx[1], &cx[1]);
        sincosf(PI_F * px2, &sx[2], &cx[2]);
        sincosf(PI_F * px3, &sx[3], &cx[3]);

        float v0r[4], v0i[4], v1r[4], v1i[4];
        #pragma unroll
        for (int q = 0; q < 4; q++) {
            const float4 u = ssu2[q];
            v0r[q] = u.x * cx[q] + u.w * sx[q];
            v0i[q] = u.y * cx[q] + u.z * sx[q];
            v1r[q] = u.z * cx[q] - u.y * sx[q];
            v1i[q] = u.w * cx[q] - u.x * sx[q];
        }

        // w01[m], m = (q0bit<<1)|q1bit
        float w01r[4], w01i[4];
        #pragma unroll
        for (int m = 0; m < 4; m++) {
            const float x0r = (m & 2) ? v1r[0] : v0r[0], x0i = (m & 2) ? v1i[0] : v0i[0];
            const float x1r = (m & 1) ? v1r[1] : v0r[1], x1i = (m & 1) ? v1i[1] : v0i[1];
            w01r[m] = x0r * x1r - x0i * x1i;
            w01i[m] = x0r * x1i + x0i * x1r;
        }
        // t2[j] = v(q2)_j (x) v(q3)_e,  j = q2 bit
        const float v3r = e ? v1r[3] : v0r[3], v3i = e ? v1i[3] : v0i[3];
        float t2r[2], t2i[2];
        #pragma unroll
        for (int j = 0; j < 2; j++) {
            const float y2r = j ? v1r[2] : v0r[2], y2i = j ? v1i[2] : v0i[2];
            t2r[j] = y2r * v3r - y2i * v3i;
            t2i[j] = y2r * v3i + y2i * v3r;
        }
        // h[k] = amp(2k+e): h[k] = w01[k>>1] (x) t2[k&1]
        float hr[8], hi[8];
        #pragma unroll
        for (int k = 0; k < 8; k++) {
            const int m = k >> 1, j = k & 1;
            hr[k] = w01r[m] * t2r[j] - w01i[m] * t2i[j];
            hi[k] = w01r[m] * t2i[j] + w01i[m] * t2r[j];
        }

        // Layers 1..4: CNOT ring then merged SU(2) per qubit.
        #pragma unroll
        for (int layer = 1; layer < 5; layer++) {
            // --- CNOT ring 0->1->2->3->0 ---
            // CNOT(q0->q1): k bit2 controls k bit1: swap (4,6),(5,7) (local rename)
            { float tr, ti;
              tr = hr[4]; hr[4] = hr[6]; hr[6] = tr;  ti = hi[4]; hi[4] = hi[6]; hi[6] = ti;
              tr = hr[5]; hr[5] = hr[7]; hr[7] = tr;  ti = hi[5]; hi[5] = hi[7]; hi[7] = ti; }
            // CNOT(q1->q2): k bit1 controls k bit0: swap (2,3),(6,7) (local rename)
            { float tr, ti;
              tr = hr[2]; hr[2] = hr[3]; hr[3] = tr;  ti = hi[2]; hi[2] = hi[3]; hi[3] = ti;
              tr = hr[6]; hr[6] = hr[7]; hr[7] = tr;  ti = hi[6]; hi[6] = hi[7]; hi[7] = ti; }
            // CNOT(q2->q3): k bit0 controls amp bit0: cross-thread swap for odd k
            #pragma unroll
            for (int k = 1; k < 8; k += 2) {
                hr[k] = __shfl_xor_sync(wmask, hr[k], 1);
                hi[k] = __shfl_xor_sync(wmask, hi[k], 1);
            }
            // CNOT(q3->q0): amp bit0 (e==1) controls k bit2: predicated swap k<->k|4
            #pragma unroll
            for (int k = 0; k < 4; k++) {
                const float ar0 = hr[k], ai0 = hi[k], ar1 = hr[k + 4], ai1 = hi[k + 4];
                hr[k]     = e ? ar1 : ar0;  hi[k]     = e ? ai1 : ai0;
                hr[k + 4] = e ? ar0 : ar1;  hi[k + 4] = e ? ai0 : ai1;
            }

            // --- local gates on q0 (k bit2), q1 (k bit1), q2 (k bit0) ---
            #pragma unroll
            for (int q = 0; q < 3; q++) {
                const float4 u = ssu2[layer * 4 + q];
                const int st = 4 >> q;
                #pragma unroll
                for (int k = 0; k < 8; k++) {
                    if (k & st) continue;
                    const int j = k | st;
                    const float a0r = hr[k], a0i = hi[k], a1r = hr[j], a1i = hi[j];
                    hr[k] = u.x * a0r - u.y * a0i - u.z * a1r - u.w * a1i;
                    hi[k] = u.x * a0i + u.y * a0r - u.z * a1i + u.w * a1r;
                    hr[j] = u.z * a0r - u.w * a0i + u.x * a1r + u.y * a1i;
                    hi[j] = u.z * a0i + u.w * a0r + u.x * a1i - u.y * a1r;
                }
            }
            // --- gate on q3 (split qubit): partner exchange + signed update ---
            {
                const float4 u = ssu2[layer * 4 + 3];
                const float ys = s * u.y, zs = s * u.z;
                float pr[8], pi2[8];
                #pragma unroll
                for (int k = 0; k < 8; k++) {
                    pr[k]  = __shfl_xor_sync(wmask, hr[k], 1);
                    pi2[k] = __shfl_xor_sync(wmask, hi[k], 1);
                }
                #pragma unroll
                for (int k = 0; k < 8; k++) {
                    const float orr = hr[k], oii = hi[k];
                    hr[k] = u.x * orr + ys * oii + zs * pr[k]  - u.w * pi2[k];
                    hi[k] = u.x * oii - ys * orr + zs * pi2[k] + u.w * pr[k];
                }
            }
        }

        // <Z_q> partials from this thread's 8 probabilities
        float p[8];
        #pragma unroll
        for (int k = 0; k < 8; k++) p[k] = hr[k] * hr[k] + hi[k] * hi[k];
        float eq[4];
        #pragma unroll
        for (int q = 0; q < 3; q++) {
            const int st = 4 >> q;
            float acc = 0.f;
            #pragma unroll
            for (int k = 0; k < 8; k++) acc += (k & st) ? -p[k] : p[k];
            eq[q] = acc;
        }
        {
            float acc = 0.f;
            #pragma unroll
            for (int k = 0; k < 8; k++) acc += p[k];
            eq[3] = e ? -acc : acc;
        }
        // pairwise reduce + store (e==0 writes)
        #pragma unroll
        for (int q = 0; q < 4; q++) eq[q] += __shfl_xor_sync(wmask, eq[q], 1);
        if (e == 0) {
            sfeat[patch * 4 + 0] = eq[0];
            sfeat[patch * 4 + 1] = eq[1];
            sfeat[patch * 4 + 2] = eq[2];
            sfeat[patch * 4 + 3] = eq[3];
        }
    }
    __syncthreads();

    // FC1: 64 outputs, each computed by 8 threads over 98-float k-slices (float2).
    {
        const int o = t >> 3, part = t & 7;
        const float2* wrow = (const float2*)(fc1_w + o * 784 + part * 98);
        const float2* frow = (const float2*)(sfeat + part * 98);
        float sum = 0.f;
        #pragma unroll 7
        for (int k = 0; k < 49; k++) {
            const float2 w2 = wrow[k];
            const float2 f2 = frow[k];
            sum += w2.x * f2.x + w2.y * f2.y;
        }
        sum += __shfl_xor_sync(0xffffffffu, sum, 1);
        sum += __shfl_xor_sync(0xffffffffu, sum, 2);
        sum += __shfl_xor_sync(0xffffffffu, sum, 4);
        if (part == 0) sh[o] = fmaxf(sum + fc1_b[o], 0.f);
    }
    __syncthreads();

    // FC2: 10 outputs
    if (t < 10) {
        float sum = fc2_b[t];
        const float* w2 = fc2_w + t * 64;
        #pragma unroll
        for (int k = 0; k < 64; k++) sum += w2[k] * sh[k];
        out[b * 10 + t] = sum;
    }
}

extern "C" void kernel_launch(void* const* d_in, const int* in_sizes, int n_in,
                              void* d_out, int out_size) {
    const float* x      = (const float*)d_in[0];
    const float* weight = (const float*)d_in[1];
    const float* fc1_w  = (const float*)d_in[2];
    const float* fc1_b  = (const float*)d_in[3];
    const float* fc2_w  = (const float*)d_in[4];
    const float* fc2_b  = (const float*)d_in[5];
    float* out = (float*)d_out;

    const int B = in_sizes[0] / 784;  // 128
    qnet_kernel<<<B, 512>>>(x, weight, fc1_w, fc1_b, fc2_w, fc2_b, out);
}

// round 6
// speedup vs baseline: 1.0056x; 1.0056x over previous
#include <cuda_runtime.h>
#include <math.h>

#define PI_F 3.14159265358979323846f

typedef unsigned long long u64;

__device__ __forceinline__ u64 pk2(float lo, float hi) {
    u64 r; asm("mov.b64 %0, {%1, %2};" : "=l"(r) : "f"(lo), "f"(hi)); return r;
}
__device__ __forceinline__ void upk2(float& lo, float& hi, u64 v) {
    asm("mov.b64 {%0, %1}, %2;" : "=f"(lo), "=f"(hi) : "l"(v));
}
__device__ __forceinline__ u64 fma2(u64 a, u64 b, u64 c) {
    u64 r; asm("fma.rn.f32x2 %0, %1, %2, %3;" : "=l"(r) : "l"(a), "l"(b), "l"(c)); return r;
}
__device__ __forceinline__ u64 mul2(u64 a, u64 b) {
    u64 r; asm("mul.rn.f32x2 %0, %1, %2;" : "=l"(r) : "l"(a), "l"(b)); return r;
}
__device__ __forceinline__ u64 swap2(u64 v) {   // (lo,hi) -> (hi,lo): register renaming
    float lo, hi; upk2(lo, hi, v); return pk2(hi, lo);
}

// One block per batch image (128 blocks x 256 threads), 1 thread per patch.
// State packing: amp bit0 (= qubit 3) is the f32x2 lane; R[m]/I[m] hold amps
// (2m, 2m+1). Gates on q0..q2 use broadcast coefficient packs (2x fewer issue
// slots via FFMA2); the q3 gate uses sign-packed coefficients + free lane swap.
// All 4 ring CNOTs are pure register renames.
__global__ __launch_bounds__(256, 1) void qnet_kernel(
    const float* __restrict__ x,      // [128,1,28,28]
    const float* __restrict__ weight, // [60]
    const float* __restrict__ fc1_w,  // [64,784]
    const float* __restrict__ fc1_b,  // [64]
    const float* __restrict__ fc2_w,  // [10,64]
    const float* __restrict__ fc2_b,  // [10]
    float* __restrict__ out)          // [128,10]
{
    __shared__ float4 ssu2l0[4];      // layer-0 SU(2) (scalar, absorbed into init)
    __shared__ u64 spk[4][27];        // layers 1..4 packed gate coefficients
    __shared__ float sfeat[784];
    __shared__ float sh[64];

    const int t = threadIdx.x;
    const int b = blockIdx.x;

    // U = Ry(c)*Rz(bb)*Ry(a) = [[alpha, -conj(beta)],[beta, conj(alpha)]]
    // alpha = (ar, ai), beta = (br, bi)
    if (t < 20) {
        const int layer = t >> 2, q = t & 3;
        const int base = layer * 12;
        float sa, ca, sb, cb, sc, cc;
        sincosf(0.5f * weight[base + q],     &sa, &ca);
        sincosf(0.5f * weight[base + 4 + q], &sb, &cb);
        sincosf(0.5f * weight[base + 8 + q], &sc, &cc);
        const float ar =  cb * (cc * ca - sc * sa);
        const float ai = -sb * (cc * ca + sc * sa);
        const float br =  cb * (sc * ca + cc * sa);
        const float bi =  sb * (cc * sa - sc * ca);
        if (layer == 0) {
            ssu2l0[q] = make_float4(ar, ai, br, bi);
        } else if (q < 3) {
            u64* d = spk[layer - 1] + q * 7;
            d[0] = pk2(ar, ar);                       // PX
            d[1] = pk2(ai, ai);   d[2] = pk2(-ai, -ai); // PY, PNY
            d[3] = pk2(br, br);   d[4] = pk2(-br, -br); // PZ, PNZ
            d[5] = pk2(bi, bi);   d[6] = pk2(-bi, -bi); // PW, PNW
        } else {
            u64* d = spk[layer - 1] + 21;
            d[0] = pk2(ar, ar);                       // XX
            d[1] = pk2(-ai, ai);  d[2] = pk2(ai, -ai);  // YMP, YPM
            d[3] = pk2(-br, br);                      // ZMP
            d[4] = pk2(-bi, -bi); d[5] = pk2(bi, bi);   // WMM, WPP
        }
    }
    __syncthreads();

    if (t < 196) {
        const int pi_ = t / 14, pj = t % 14;
        const float* xb = x + b * 784 + (2 * pi_) * 28 + 2 * pj;
        const float px0 = xb[0], px1 = xb[1], px2 = xb[28], px3 = xb[29];

        // Rx(2*pi*x)|0> = (cos(pi x), -i sin(pi x)); apply layer-0 U_q directly.
        float cx[4], sx[4];
        sincosf(PI_F * px0, &sx[0], &cx[0]);
        sincosf(PI_F * px1, &sx[1], &cx[1]);
        sincosf(PI_F * px2, &sx[2], &cx[2]);
        sincosf(PI_F * px3, &sx[3], &cx[3]);

        float v0r[4], v0i[4], v1r[4], v1i[4];
        #pragma unroll
        for (int q = 0; q < 4; q++) {
            const float4 u = ssu2l0[q];
            v0r[q] = u.x * cx[q] + u.w * sx[q];
            v0i[q] = u.y * cx[q] + u.z * sx[q];
            v1r[q] = u.z * cx[q] - u.y * sx[q];
            v1i[q] = u.w * cx[q] - u.x * sx[q];
        }

        // Product state via tree: w01 (q0 x q1), w23 (q2 x q3)
        float w01r[4], w01i[4], w23r[4], w23i[4];
        #pragma unroll
        for (int b0 = 0; b0 < 2; b0++) {
            const float x0r = b0 ? v1r[0] : v0r[0], x0i = b0 ? v1i[0] : v0i[0];
            const float y0r = b0 ? v1r[2] : v0r[2], y0i = b0 ? v1i[2] : v0i[2];
            #pragma unroll
            for (int b1 = 0; b1 < 2; b1++) {
                const float x1r = b1 ? v1r[1] : v0r[1], x1i = b1 ? v1i[1] : v0i[1];
                const float y1r = b1 ? v1r[3] : v0r[3], y1i = b1 ? v1i[3] : v0i[3];
                w01r[b0 * 2 + b1] = x0r * x1r - x0i * x1i;
                w01i[b0 * 2 + b1] = x0r * x1i + x0i * x1r;
                w23r[b0 * 2 + b1] = y0r * y1r - y0i * y1i;
                w23i[b0 * 2 + b1] = y0r * y1i + y0i * y1r;
            }
        }

        // Packed state: R[m]/I[m] = amps (2m, 2m+1); m bits = (q0,q1,q2), lane = q3
        u64 R[8], I[8];
        #pragma unroll
        for (int m = 0; m < 8; m++) {
            const int hi2 = m >> 1;          // (q0,q1) index into w01
            const int q2b = m & 1;           // q2 bit
            const int lo0 = q2b * 2 + 0, lo1 = q2b * 2 + 1;  // (q2,q3) index into w23
            const float e0r = w01r[hi2] * w23r[lo0] - w01i[hi2] * w23i[lo0];
            const float e0i = w01r[hi2] * w23i[lo0] + w01i[hi2] * w23r[lo0];
            const float e1r = w01r[hi2] * w23r[lo1] - w01i[hi2] * w23i[lo1];
            const float e1i = w01r[hi2] * w23i[lo1] + w01i[hi2] * w23r[lo1];
            R[m] = pk2(e0r, e1r);
            I[m] = pk2(e0i, e1i);
        }

        // Layers 1..4: CNOT ring (all renames) then merged SU(2) per qubit.
        #pragma unroll 1
        for (int layer = 1; layer < 5; layer++) {
            const u64* g = spk[layer - 1];

            // CNOT(q0->q1): m bit2 controls m bit1: swap m 4<->6, 5<->7
            { u64 tmp;
              tmp = R[4]; R[4] = R[6]; R[6] = tmp;  tmp = I[4]; I[4] = I[6]; I[6] = tmp;
              tmp = R[5]; R[5] = R[7]; R[7] = tmp;  tmp = I[5]; I[5] = I[7]; I[7] = tmp; }
            // CNOT(q1->q2): m bit1 controls m bit0: swap m 2<->3, 6<->7
            { u64 tmp;
              tmp = R[2]; R[2] = R[3]; R[3] = tmp;  tmp = I[2]; I[2] = I[3]; I[3] = tmp;
              tmp = R[6]; R[6] = R[7]; R[7] = tmp;  tmp = I[6]; I[6] = I[7]; I[7] = tmp; }
            // CNOT(q2->q3): m bit0 controls lane: lane-swap odd packs
            R[1] = swap2(R[1]); R[3] = swap2(R[3]); R[5] = swap2(R[5]); R[7] = swap2(R[7]);
            I[1] = swap2(I[1]); I[3] = swap2(I[3]); I[5] = swap2(I[5]); I[7] = swap2(I[7]);
            // CNOT(q3->q0): lane1 controls m bit2: exchange hi lanes of m <-> m+4
            #pragma unroll
            for (int m = 0; m < 4; m++) {
                float l0, h0, l1, h1;
                upk2(l0, h0, R[m]); upk2(l1, h1, R[m + 4]);
                R[m] = pk2(l0, h1); R[m + 4] = pk2(l1, h0);
                upk2(l0, h0, I[m]); upk2(l1, h1, I[m + 4]);
                I[m] = pk2(l0, h1); I[m + 4] = pk2(l1, h0);
            }

            // Gates on q0 (m bit2), q1 (m bit1), q2 (m bit0): packed, both lanes same.
            #pragma unroll
            for (int q = 0; q < 3; q++) {
                const u64 PX  = g[q * 7 + 0];
                const u64 PY  = g[q * 7 + 1], PNY = g[q * 7 + 2];
                const u64 PZ  = g[q * 7 + 3], PNZ = g[q * 7 + 4];
                const u64 PW  = g[q * 7 + 5], PNW = g[q * 7 + 6];
                const int st = 4 >> q;
                #pragma unroll
                for (int m = 0; m < 8; m++) {
                    if (m & st) continue;
                    const int j = m | st;
                    const u64 R0 = R[m], I0 = I[m], R1 = R[j], I1 = I[j];
                    R[m] = fma2(PNW, I1, fma2(PNZ, R1, fma2(PNY, I0, mul2(PX, R0))));
                    I[m] = fma2(PW,  R1, fma2(PNZ, I1, fma2(PY,  R0, mul2(PX, I0))));
                    R[j] = fma2(PY,  I1, fma2(PX,  R1, fma2(PNW, I0, mul2(PZ, R0))));
                    I[j] = fma2(PNY, R1, fma2(PX,  I1, fma2(PW,  R0, mul2(PZ, I0))));
                }
            }
            // Gate on q3 (lane dim): sign-packed coefficients + free lane swap.
            {
                const u64 XX  = g[21], YMP = g[22], YPM = g[23];
                const u64 ZMP = g[24], WMM = g[25], WPP = g[26];
                #pragma unroll
                for (int m = 0; m < 8; m++) {
                    const u64 Rs = swap2(R[m]), Is = swap2(I[m]);
                    const u64 nR = fma2(WMM, Is, fma2(ZMP, Rs, fma2(YMP, I[m], mul2(XX, R[m]))));
                    const u64 nI = fma2(WPP, Rs, fma2(ZMP, Is, fma2(YPM, R[m], mul2(XX, I[m]))));
                    R[m] = nR; I[m] = nI;
                }
            }
        }

        // Probabilities (packed) and <Z_q> expectations
        float pl[8], ph[8];
        #pragma unroll
        for (int m = 0; m < 8; m++) {
            const u64 P = fma2(I[m], I[m], mul2(R[m], R[m]));
            upk2(pl[m], ph[m], P);
        }
        float e0 = 0.f, e1 = 0.f, e2 = 0.f, e3 = 0.f;
        #pragma unroll
        for (int m = 0; m < 8; m++) {
            const float ps = pl[m] + ph[m];
            e0 += (m & 4) ? -ps : ps;
            e1 += (m & 2) ? -ps : ps;
            e2 += (m & 1) ? -ps : ps;
            e3 += pl[m] - ph[m];
        }
        sfeat[t * 4 + 0] = e0;
        sfeat[t * 4 + 1] = e1;
        sfeat[t * 4 + 2] = e2;
        sfeat[t * 4 + 3] = e3;
    }
    __syncthreads();

    // FC1: 64 outputs, each computed by 4 threads over 196-float k-slices (float4).
    {
        const int o = t >> 2, part = t & 3;
        const float4* wrow = (const float4*)(fc1_w + o * 784 + part * 196);
        const float4* frow = (const float4*)(sfeat + part * 196);
        float sum = 0.f;
        #pragma unroll 7
        for (int k = 0; k < 49; k++) {
            float4 w4 = wrow[k];
            float4 f4 = frow[k];
            sum += w4.x * f4.x + w4.y * f4.y + w4.z * f4.z + w4.w * f4.w;
        }
        sum += __shfl_xor_sync(0xffffffffu, sum, 1);
        sum += __shfl_xor_sync(0xffffffffu, sum, 2);
        if (part == 0) sh[o] = fmaxf(sum + fc1_b[o], 0.f);
    }
    __syncthreads();

    // FC2: 10 outputs
    if (t < 10) {
        float sum = fc2_b[t];
        const float* w2 = fc2_w + t * 64;
        #pragma unroll
        for (int k = 0; k < 64; k++) sum += w2[k] * sh[k];
        out[b * 10 + t] = sum;
    }
}

extern "C" void kernel_launch(void* const* d_in, const int* in_sizes, int n_in,
                              void* d_out, int out_size) {
    const float* x      = (const float*)d_in[0];
    const float* weight = (const float*)d_in[1];
    const float* fc1_w  = (const float*)d_in[2];
    const float* fc1_b  = (const float*)d_in[3];
    const float* fc2_w  = (const float*)d_in[4];
    const float* fc2_b  = (const float*)d_in[5];
    float* out = (float*)d_out;

    const int B = in_sizes[0] / 784;  // 128
    qnet_kernel<<<B, 256>>>(x, weight, fc1_w, fc1_b, fc2_w, fc2_b, out);
}

// round 7
// speedup vs baseline: 1.1520x; 1.1456x over previous
#include <cuda_runtime.h>
#include <math.h>

#define PI_F 3.14159265358979323846f

// One block per batch image (128 blocks x 256 threads), 1 thread per patch.
// Euler-merged SU(2) per (layer,qubit); layer 0 absorbed into the initial
// product state; CNOT ring = register renames. Fast-path trig (__sincosf):
// all args in [0, pi), abs err ~1e-6 << 1e-3 tolerance.
__global__ __launch_bounds__(256, 1) void qnet_kernel(
    const float* __restrict__ x,      // [128,1,28,28]
    const float* __restrict__ weight, // [60]
    const float* __restrict__ fc1_w,  // [64,784]
    const float* __restrict__ fc1_b,  // [64]
    const float* __restrict__ fc2_w,  // [10,64]
    const float* __restrict__ fc2_b,  // [10]
    float* __restrict__ out)          // [128,10]
{
    __shared__ float4 ssu2[20];       // (ar, ai, br, bi) per (layer*4 + qubit)
    __shared__ float sfeat[784];
    __shared__ float sh[64];

    const int t = threadIdx.x;
    const int b = blockIdx.x;

    // U = Ry(c)*Rz(bb)*Ry(a) = [[alpha, -conj(beta)],[beta, conj(alpha)]]
    if (t < 20) {
        const int layer = t >> 2, q = t & 3;
        const int base = layer * 12;
        float sa, ca, sb, cb, sc, cc;
        __sincosf(0.5f * weight[base + q],     &sa, &ca);
        __sincosf(0.5f * weight[base + 4 + q], &sb, &cb);
        __sincosf(0.5f * weight[base + 8 + q], &sc, &cc);
        const float ar =  cb * (cc * ca - sc * sa);
        const float ai = -sb * (cc * ca + sc * sa);
        const float br =  cb * (sc * ca + cc * sa);
        const float bi =  sb * (cc * sa - sc * ca);
        ssu2[t] = make_float4(ar, ai, br, bi);
    }
    __syncthreads();

    if (t < 196) {
        const int pi_ = t / 14, pj = t % 14;
        const float* xb = x + b * 784 + (2 * pi_) * 28 + 2 * pj;
        const float px0 = xb[0], px1 = xb[1], px2 = xb[28], px3 = xb[29];

        // Rx(2*pi*x)|0> = (cos(pi x), -i sin(pi x)); apply layer-0 U_q directly.
        float cx[4], sx[4];
        __sincosf(PI_F * px0, &sx[0], &cx[0]);
        __sincosf(PI_F * px1, &sx[1], &cx[1]);
        __sincosf(PI_F * px2, &sx[2], &cx[2]);
        __sincosf(PI_F * px3, &sx[3], &cx[3]);

        float v0r[4], v0i[4], v1r[4], v1i[4];
        #pragma unroll
        for (int q = 0; q < 4; q++) {
            const float4 u = ssu2[q];
            // v0 = alpha*cx + i*conj(beta)*sx ; v1 = beta*cx - i*conj(alpha)*sx
            v0r[q] = u.x * cx[q] + u.w * sx[q];
            v0i[q] = u.y * cx[q] + u.z * sx[q];
            v1r[q] = u.z * cx[q] - u.y * sx[q];
            v1i[q] = u.w * cx[q] - u.x * sx[q];
        }

        // Product state via tree: w01 = v(q0) x v(q1), w23 = v(q2) x v(q3)
        float w01r[4], w01i[4], w23r[4], w23i[4];
        #pragma unroll
        for (int b0 = 0; b0 < 2; b0++) {
            const float x0r = b0 ? v1r[0] : v0r[0], x0i = b0 ? v1i[0] : v0i[0];
            const float y0r = b0 ? v1r[2] : v0r[2], y0i = b0 ? v1i[2] : v0i[2];
            #pragma unroll
            for (int b1 = 0; b1 < 2; b1++) {
                const float x1r = b1 ? v1r[1] : v0r[1], x1i = b1 ? v1i[1] : v0i[1];
                const float y1r = b1 ? v1r[3] : v0r[3], y1i = b1 ? v1i[3] : v0i[3];
                w01r[b0 * 2 + b1] = x0r * x1r - x0i * x1i;
                w01i[b0 * 2 + b1] = x0r * x1i + x0i * x1r;
                w23r[b0 * 2 + b1] = y0r * y1r - y0i * y1i;
                w23i[b0 * 2 + b1] = y0r * y1i + y0i * y1r;
            }
        }

        // a[i], i = (q0 q1 q2 q3) bits (q0 = bit3)
        float ar[16], ai[16];
        #pragma unroll
        for (int i = 0; i < 16; i++) {
            const int hi = i >> 2, lo = i & 3;
            ar[i] = w01r[hi] * w23r[lo] - w01i[hi] * w23i[lo];
            ai[i] = w01r[hi] * w23i[lo] + w01i[hi] * w23r[lo];
        }

        // Prefetch layer-1 gates; inside the loop prefetch next layer's gates
        // before doing this layer's arithmetic (hide LDS latency).
        float4 g0 = ssu2[4], g1 = ssu2[5], g2 = ssu2[6], g3 = ssu2[7];

        // Layers 1..4: CNOT ring then merged SU(2) per qubit (fully unrolled).
        #pragma unroll
        for (int layer = 1; layer < 5; layer++) {
            const float4 u0 = g0, u1 = g1, u2 = g2, u3 = g3;
            if (layer < 4) {
                g0 = ssu2[layer * 4 + 4]; g1 = ssu2[layer * 4 + 5];
                g2 = ssu2[layer * 4 + 6]; g3 = ssu2[layer * 4 + 7];
            }
            // CNOT ring 0->1->2->3->0 (register renames)
            #pragma unroll
            for (int q = 0; q < 4; q++) {
                const int cb = 8 >> q, tb = 8 >> ((q + 1) & 3);
                #pragma unroll
                for (int i = 0; i < 16; i++) {
                    if ((i & cb) && !(i & tb)) {
                        const int j = i | tb;
                        float tr = ar[i]; ar[i] = ar[j]; ar[j] = tr;
                        float ti = ai[i]; ai[i] = ai[j]; ai[j] = ti;
                    }
                }
            }
            // U per qubit: a0' = alpha a0 - conj(beta) a1 ; a1' = beta a0 + conj(alpha) a1
            #pragma unroll
            for (int q = 0; q < 4; q++) {
                const float4 u = (q == 0) ? u0 : (q == 1) ? u1 : (q == 2) ? u2 : u3;
                const int st = 8 >> q;
                #pragma unroll
                for (int i = 0; i < 16; i++) {
                    if (i & st) continue;
                    const int j = i | st;
                    const float a0r = ar[i], a0i = ai[i], a1r = ar[j], a1i = ai[j];
                    ar[i] = u.x * a0r - u.y * a0i - u.z * a1r - u.w * a1i;
                    ai[i] = u.x * a0i + u.y * a0r - u.z * a1i + u.w * a1r;
                    ar[j] = u.z * a0r - u.w * a0i + u.x * a1r + u.y * a1i;
                    ai[j] = u.z * a0i + u.w * a0r + u.x * a1i - u.y * a1r;
                }
            }
        }

        // <Z_q> expectations
        float p[16];
        #pragma unroll
        for (int i = 0; i < 16; i++) p[i] = ar[i] * ar[i] + ai[i] * ai[i];
        float e[4];
        #pragma unroll
        for (int q = 0; q < 4; q++) {
            const int st = 8 >> q;
            float acc = 0.f;
            #pragma unroll
            for (int i = 0; i < 16; i++) acc += (i & st) ? -p[i] : p[i];
            e[q] = acc;
        }
        *(float4*)&sfeat[t * 4] = make_float4(e[0], e[1], e[2], e[3]);
    }
    __syncthreads();

    // FC1: 64 outputs, each computed by 4 threads over 196-long k-slices (float4).
    {
        const int o = t >> 2, part = t & 3;
        const float4* wrow = (const float4*)(fc1_w + o * 784 + part * 196);
        const float4* frow = (const float4*)(sfeat + part * 196);
        float sum = 0.f;
        #pragma unroll 7
        for (int k = 0; k < 49; k++) {
            float4 w4 = wrow[k];
            float4 f4 = frow[k];
            sum += w4.x * f4.x + w4.y * f4.y + w4.z * f4.z + w4.w * f4.w;
        }
        sum += __shfl_xor_sync(0xffffffffu, sum, 1);
        sum += __shfl_xor_sync(0xffffffffu, sum, 2);
        if (part == 0) sh[o] = fmaxf(sum + fc1_b[o], 0.f);
    }
    __syncthreads();

    // FC2: 10 outputs
    if (t < 10) {
        float sum = fc2_b[t];
        const float* w2 = fc2_w + t * 64;
        #pragma unroll
        for (int k = 0; k < 64; k++) sum += w2[k] * sh[k];
        out[b * 10 + t] = sum;
    }
}

extern "C" void kernel_launch(void* const* d_in, const int* in_sizes, int n_in,
                              void* d_out, int out_size) {
    const float* x      = (const float*)d_in[0];
    const float* weight = (const float*)d_in[1];
    const float* fc1_w  = (const float*)d_in[2];
    const float* fc1_b  = (const float*)d_in[3];
    const float* fc2_w  = (const float*)d_in[4];
    const float* fc2_b  = (const float*)d_in[5];
    float* out = (float*)d_out;

    const int B = in_sizes[0] / 784;  // 128
    qnet_kernel<<<B, 256>>>(x, weight, fc1_w, fc1_b, fc2_w, fc2_b, out);
}